// round 14
// baseline (speedup 1.0000x reference)
#include <cuda_runtime.h>
#include <cstdint>

#define Tn  512
#define Bn  1024
#define Sn  64
#define An  16
#define Hn  128
#define TBn (Tn*Bn)

typedef unsigned long long ull;

__device__ float g_gx[(size_t)TBn * 384];      // gate preactivations [T*B, 3H]
__device__ float g_hidden[(size_t)TBn * Hn];   // hidden states [T*B, H]

// ---------------------------------------------------------------------------
// f32x2 + fast-math helpers
// ---------------------------------------------------------------------------
__device__ __forceinline__ ull pack2(float lo, float hi) {
    ull r;
    asm("mov.b64 %0, {%1, %2};" : "=l"(r)
        : "r"(__float_as_uint(lo)), "r"(__float_as_uint(hi)));
    return r;
}
__device__ __forceinline__ ull dup2(float v) { return pack2(v, v); }
__device__ __forceinline__ void unpack2(ull p, float& lo, float& hi) {
    unsigned int a, b;
    asm("mov.b64 {%0, %1}, %2;" : "=r"(a), "=r"(b) : "l"(p));
    lo = __uint_as_float(a); hi = __uint_as_float(b);
}
__device__ __forceinline__ void fma2(ull& d, ull a, ull b) {
    asm("fma.rn.f32x2 %0, %1, %2, %3;" : "=l"(d) : "l"(a), "l"(b), "l"(d));
}
__device__ __forceinline__ ull add2(ull a, ull b) {
    ull d;
    asm("add.rn.f32x2 %0, %1, %2;" : "=l"(d) : "l"(a), "l"(b));
    return d;
}
__device__ __forceinline__ float tanh_fast(float x) {
    float y; asm("tanh.approx.f32 %0, %1;" : "=f"(y) : "f"(x)); return y;
}
__device__ __forceinline__ float sigmoid_fast(float x) {
    return fmaf(0.5f, tanh_fast(0.5f * x), 0.5f);
}

// ---------------------------------------------------------------------------
// Encoder: fused x -> h1 -> h2 -> gx.  512 threads, 128 rows/block, 2 blk/SM.
// 8x4 microtile, in-place ABUF. a-operand SHFL-DISTRIBUTED:
// per 4-k group, lane (ks=l>>3, r=l&7) loads ONE float aT[k0+ks][rg*8+r]
// (1 lane-coalesced LDS = ~4 wf, replaces 32 wf of broadcast), then shfl.idx
// rebuilds row values in all lanes. Crossbar/k drops 12->5 wf per warp.
// ---------------------------------------------------------------------------
#define SA 132

__device__ __forceinline__ void enc_gemm64(const float* __restrict__ ap,  // aT + rg*8
                                           const float* __restrict__ wp,  // Wt + 4*cg
                                           ull acc[4][4], int lane)
{
    int ks = lane >> 3;      // which of 4 k's this lane fetches
    int rs = lane & 7;       // which row this lane fetches
    #pragma unroll 2
    for (int k4 = 0; k4 < 16; k4++) {
        int k0 = k4 * 4;
        float aval = ap[(k0 + ks) * SA + rs];
        #pragma unroll
        for (int kk = 0; kk < 4; kk++) {
            int src = kk * 8;
            float r0 = __shfl_sync(0xffffffffu, aval, src + 0);
            float r1 = __shfl_sync(0xffffffffu, aval, src + 1);
            float r2 = __shfl_sync(0xffffffffu, aval, src + 2);
            float r3 = __shfl_sync(0xffffffffu, aval, src + 3);
            float r4 = __shfl_sync(0xffffffffu, aval, src + 4);
            float r5 = __shfl_sync(0xffffffffu, aval, src + 5);
            float r6 = __shfl_sync(0xffffffffu, aval, src + 6);
            float r7 = __shfl_sync(0xffffffffu, aval, src + 7);
            ull a01 = pack2(r0, r1), a23 = pack2(r2, r3);
            ull a45 = pack2(r4, r5), a67 = pack2(r6, r7);
            float4 wv = *(const float4*)(wp + (k0 + kk) * SA);
            ull w0 = dup2(wv.x), w1 = dup2(wv.y), w2 = dup2(wv.z), w3 = dup2(wv.w);
            fma2(acc[0][0], a01, w0); fma2(acc[1][0], a23, w0);
            fma2(acc[2][0], a45, w0); fma2(acc[3][0], a67, w0);
            fma2(acc[0][1], a01, w1); fma2(acc[1][1], a23, w1);
            fma2(acc[2][1], a45, w1); fma2(acc[3][1], a67, w1);
            fma2(acc[0][2], a01, w2); fma2(acc[1][2], a23, w2);
            fma2(acc[2][2], a45, w2); fma2(acc[3][2], a67, w2);
            fma2(acc[0][3], a01, w3); fma2(acc[1][3], a23, w3);
            fma2(acc[2][3], a45, w3); fma2(acc[3][3], a67, w3);
        }
    }
}

__global__ void __launch_bounds__(512, 2) encoder_kernel(
    const float* __restrict__ x,
    const float* __restrict__ W1, const float* __restrict__ b1,
    const float* __restrict__ W2, const float* __restrict__ b2,
    const float* __restrict__ Wih, const float* __restrict__ bih)
{
    extern __shared__ float sm[];
    float* Wt   = sm;                   // 64*132 floats
    float* ABUF = sm + 64 * SA;         // 128*132 floats

    int tid  = threadIdx.x;
    int lane = tid & 31;
    int cg   = tid & 31;
    int rg   = tid >> 5;
    size_t base = (size_t)blockIdx.x * 128;

    for (int idx = tid; idx < 128 * 64; idx += 512) {
        int r = idx >> 6, k = idx & 63;
        ABUF[k * SA + r] = x[(base + r) * 64 + k];
    }
    for (int idx = tid; idx < 64 * 128; idx += 512) {
        int k = idx & 63, j = idx >> 6;
        Wt[k * SA + j] = W1[j * 64 + k];
    }
    __syncthreads();

    ull acc[4][4];

    // Phase A
    #pragma unroll
    for (int c = 0; c < 4; c++) {
        ull bb = dup2(b1[4 * cg + c]);
        acc[0][c] = bb; acc[1][c] = bb; acc[2][c] = bb; acc[3][c] = bb;
    }
    enc_gemm64(ABUF + rg * 8, Wt + 4 * cg, acc, lane);
    __syncthreads();
    #pragma unroll
    for (int c = 0; c < 4; c++) {
        int col = 4 * cg + c;
        float v[8];
        unpack2(acc[0][c], v[0], v[1]); unpack2(acc[1][c], v[2], v[3]);
        unpack2(acc[2][c], v[4], v[5]); unpack2(acc[3][c], v[6], v[7]);
        #pragma unroll
        for (int i = 0; i < 8; i++) v[i] = fmaxf(v[i], 0.f);
        *(float4*)&ABUF[col * SA + rg * 8]     = make_float4(v[0], v[1], v[2], v[3]);
        *(float4*)&ABUF[col * SA + rg * 8 + 4] = make_float4(v[4], v[5], v[6], v[7]);
    }
    __syncthreads();

    // Phase B
    #pragma unroll
    for (int c = 0; c < 4; c++) {
        ull bb = dup2(b2[4 * cg + c]);
        acc[0][c] = bb; acc[1][c] = bb; acc[2][c] = bb; acc[3][c] = bb;
    }
    #pragma unroll 1
    for (int h = 0; h < 2; h++) {
        for (int idx = tid; idx < 64 * 128; idx += 512) {
            int kl = idx & 63, j = idx >> 6;
            Wt[kl * SA + j] = W2[j * 128 + h * 64 + kl];
        }
        __syncthreads();
        enc_gemm64(ABUF + (h * 64) * SA + rg * 8, Wt + 4 * cg, acc, lane);
        __syncthreads();
    }
    #pragma unroll
    for (int c = 0; c < 4; c++) {
        int col = 4 * cg + c;
        float v[8];
        unpack2(acc[0][c], v[0], v[1]); unpack2(acc[1][c], v[2], v[3]);
        unpack2(acc[2][c], v[4], v[5]); unpack2(acc[3][c], v[6], v[7]);
        #pragma unroll
        for (int i = 0; i < 8; i++) v[i] = fmaxf(v[i], 0.f);
        *(float4*)&ABUF[col * SA + rg * 8]     = make_float4(v[0], v[1], v[2], v[3]);
        *(float4*)&ABUF[col * SA + rg * 8 + 4] = make_float4(v[4], v[5], v[6], v[7]);
    }
    __syncthreads();

    // Phase C
    #pragma unroll 1
    for (int pp = 0; pp < 3; pp++) {
        #pragma unroll
        for (int c = 0; c < 4; c++) {
            ull bb = dup2(bih[pp * 128 + 4 * cg + c]);
            acc[0][c] = bb; acc[1][c] = bb; acc[2][c] = bb; acc[3][c] = bb;
        }
        #pragma unroll 1
        for (int h = 0; h < 2; h++) {
            for (int idx = tid; idx < 64 * 128; idx += 512) {
                int kl = idx & 63, j = idx >> 6;
                Wt[kl * SA + j] = Wih[(pp * 128 + j) * 128 + h * 64 + kl];
            }
            __syncthreads();
            enc_gemm64(ABUF + (h * 64) * SA + rg * 8, Wt + 4 * cg, acc, lane);
            __syncthreads();
        }
        #pragma unroll
        for (int p = 0; p < 4; p++) {
            float va[4], vb[4];
            #pragma unroll
            for (int c = 0; c < 4; c++) unpack2(acc[p][c], va[c], vb[c]);
            size_t row0 = base + rg * 8 + 2 * p;
            *(float4*)&g_gx[row0 * 384 + pp * 128 + 4 * cg] =
                make_float4(va[0], va[1], va[2], va[3]);
            *(float4*)&g_gx[(row0 + 1) * 384 + pp * 128 + 4 * cg] =
                make_float4(vb[0], vb[1], vb[2], vb[3]);
        }
    }
}

// ---------------------------------------------------------------------------
// GRU scan (R13 measured-best, unchanged): 128 blocks x 8 rows, 256 threads.
// ---------------------------------------------------------------------------
__device__ __forceinline__ ull bfly_sum(ull x) {
    x = add2(x, __shfl_xor_sync(0xffffffffu, x, 8));
    x = add2(x, __shfl_xor_sync(0xffffffffu, x, 16));
    return x;
}
__device__ __forceinline__ ull sel4(ull a0, ull a1, ull a2, ull a3, int s) {
    ull x = (s & 1) ? a1 : a0;
    ull y = (s & 1) ? a3 : a2;
    return (s & 2) ? y : x;
}

__global__ void __launch_bounds__(256, 1) scan_kernel(
    const float* __restrict__ done, const float* __restrict__ gru0,
    const float* __restrict__ Whh, const float* __restrict__ bhh,
    float* __restrict__ out)
{
    extern __shared__ float sm[];
    float2* wln = (float2*)sm;              // 96*256 float2 = 49152 floats
    float*  hb  = sm + 49152;               // 2 * 1536 floats

    int tid  = threadIdx.x;
    int lane = tid & 31;
    int cp   = (tid >> 5) * 8 + (lane & 7); // 0..63
    int kh   = lane >> 3;                   // 0..3
    int c0   = 2 * cp, c1 = c0 + 1;
    int ra   = 2 * kh, rb = ra + 1;
    int b0   = blockIdx.x << 3;

    for (int idx = tid; idx < 96 * 256; idx += 256) {
        int kq = idx / 768;
        int rem = idx - kq * 768;
        int g = rem >> 8, t = rem & 255;
        int cpt = (t >> 5) * 8 + (t & 7);
        int kht = (t & 31) >> 3;
        int k = kht * 32 + kq;
        wln[idx] = make_float2(Whh[(g * 128 + 2 * cpt) * 128 + k],
                               Whh[(g * 128 + 2 * cpt + 1) * 128 + k]);
    }
    for (int idx = tid; idx < 1024; idx += 256) {
        int r = idx & 7, f = idx >> 3;
        hb[f * 12 + r] = gru0[(b0 + r) * 128 + f] * (1.f - done[b0 + r]);
    }
    __syncthreads();

    float brv[2] = {bhh[c0], bhh[c1]};
    float bzv[2] = {bhh[128 + c0], bhh[128 + c1]};
    float bnv[2] = {bhh[256 + c0], bhh[256 + c1]};

    float gx[2][2][3];
    #pragma unroll
    for (int rr = 0; rr < 2; rr++) {
        size_t row = (size_t)(b0 + ra + rr);
        float2 t0 = *(const float2*)&g_gx[row * 384 + c0];
        float2 t1 = *(const float2*)&g_gx[row * 384 + 128 + c0];
        float2 t2 = *(const float2*)&g_gx[row * 384 + 256 + c0];
        gx[rr][0][0] = t0.x; gx[rr][1][0] = t0.y;
        gx[rr][0][1] = t1.x; gx[rr][1][1] = t1.y;
        gx[rr][0][2] = t2.x; gx[rr][1][2] = t2.y;
    }

    const float2* wp = wln + tid;
    int cur = 0;

    for (int t = 0; t < Tn; t++) {
        float gxn[2][2][3], dn[2];
        {
            int tnx = (t + 1 < Tn) ? (t + 1) : t;
            #pragma unroll
            for (int rr = 0; rr < 2; rr++) {
                size_t row = (size_t)tnx * Bn + b0 + ra + rr;
                float2 t0 = *(const float2*)&g_gx[row * 384 + c0];
                float2 t1 = *(const float2*)&g_gx[row * 384 + 128 + c0];
                float2 t2 = *(const float2*)&g_gx[row * 384 + 256 + c0];
                gxn[rr][0][0] = t0.x; gxn[rr][1][0] = t0.y;
                gxn[rr][0][1] = t1.x; gxn[rr][1][1] = t1.y;
                gxn[rr][0][2] = t2.x; gxn[rr][1][2] = t2.y;
                dn[rr] = (t + 1 < Tn) ? done[(size_t)(t + 1) * Bn + b0 + ra + rr] : 0.f;
            }
        }

        const float* hbc = hb + cur * 1536;
        const float* hk  = hbc + (kh * 32) * 12;

        ull aR[2][4], aZ[2][4], aN[2][4];
        #pragma unroll
        for (int cc = 0; cc < 2; cc++)
            #pragma unroll
            for (int p = 0; p < 4; p++) { aR[cc][p] = 0; aZ[cc][p] = 0; aN[cc][p] = 0; }

        #pragma unroll 8
        for (int kq = 0; kq < 32; kq++) {
            ulonglong2 hA = *(const ulonglong2*)(hk + kq * 12);
            ulonglong2 hB = *(const ulonglong2*)(hk + kq * 12 + 4);
            float2 wr = wp[(kq * 3 + 0) * 256];
            float2 wz = wp[(kq * 3 + 1) * 256];
            float2 wn = wp[(kq * 3 + 2) * 256];
            ull wr0 = dup2(wr.x), wr1 = dup2(wr.y);
            ull wz0 = dup2(wz.x), wz1 = dup2(wz.y);
            ull wn0 = dup2(wn.x), wn1 = dup2(wn.y);
            fma2(aR[0][0], hA.x, wr0); fma2(aR[0][1], hA.y, wr0);
            fma2(aR[0][2], hB.x, wr0); fma2(aR[0][3], hB.y, wr0);
            fma2(aR[1][0], hA.x, wr1); fma2(aR[1][1], hA.y, wr1);
            fma2(aR[1][2], hB.x, wr1); fma2(aR[1][3], hB.y, wr1);
            fma2(aZ[0][0], hA.x, wz0); fma2(aZ[0][1], hA.y, wz0);
            fma2(aZ[0][2], hB.x, wz0); fma2(aZ[0][3], hB.y, wz0);
            fma2(aZ[1][0], hA.x, wz1); fma2(aZ[1][1], hA.y, wz1);
            fma2(aZ[1][2], hB.x, wz1); fma2(aZ[1][3], hB.y, wz1);
            fma2(aN[0][0], hA.x, wn0); fma2(aN[0][1], hA.y, wn0);
            fma2(aN[0][2], hB.x, wn0); fma2(aN[0][3], hB.y, wn0);
            fma2(aN[1][0], hA.x, wn1); fma2(aN[1][1], hA.y, wn1);
            fma2(aN[1][2], hB.x, wn1); fma2(aN[1][3], hB.y, wn1);
        }

        #pragma unroll
        for (int cc = 0; cc < 2; cc++)
            #pragma unroll
            for (int p = 0; p < 4; p++) {
                aR[cc][p] = bfly_sum(aR[cc][p]);
                aZ[cc][p] = bfly_sum(aZ[cc][p]);
                aN[cc][p] = bfly_sum(aN[cc][p]);
            }

        float sR[2][2], sZ[2][2], sN[2][2];
        #pragma unroll
        for (int cc = 0; cc < 2; cc++) {
            float lo, hi;
            unpack2(sel4(aR[cc][0], aR[cc][1], aR[cc][2], aR[cc][3], kh), lo, hi);
            sR[0][cc] = lo; sR[1][cc] = hi;
            unpack2(sel4(aZ[cc][0], aZ[cc][1], aZ[cc][2], aZ[cc][3], kh), lo, hi);
            sZ[0][cc] = lo; sZ[1][cc] = hi;
            unpack2(sel4(aN[cc][0], aN[cc][1], aN[cc][2], aN[cc][3], kh), lo, hi);
            sN[0][cc] = lo; sN[1][cc] = hi;
        }

        float2 hoA = *(const float2*)&hbc[c0 * 12 + ra];
        float2 hoB = *(const float2*)&hbc[c1 * 12 + ra];
        float ho[2][2] = {{hoA.x, hoB.x}, {hoA.y, hoB.y}};

        float hnew[2][2];
        #pragma unroll
        for (int rr = 0; rr < 2; rr++)
            #pragma unroll
            for (int cc = 0; cc < 2; cc++) {
                float sr = sR[rr][cc] + brv[cc] + gx[rr][cc][0];
                float sz = sZ[rr][cc] + bzv[cc] + gx[rr][cc][1];
                float sn = sN[rr][cc] + bnv[cc];
                float rg = sigmoid_fast(sr);
                float zg = sigmoid_fast(sz);
                float ng = tanh_fast(gx[rr][cc][2] + rg * sn);
                hnew[rr][cc] = (1.f - zg) * ng + zg * ho[rr][cc];
            }

        *(float2*)&g_hidden[((size_t)t * Bn + b0 + ra) * Hn + c0] =
            make_float2(hnew[0][0], hnew[0][1]);
        *(float2*)&g_hidden[((size_t)t * Bn + b0 + rb) * Hn + c0] =
            make_float2(hnew[1][0], hnew[1][1]);
        if (t == Tn - 1) {
            *(float2*)&out[(size_t)TBn * 3 + (b0 + ra) * Hn + c0] =
                make_float2(hnew[0][0], hnew[0][1]);
            *(float2*)&out[(size_t)TBn * 3 + (b0 + rb) * Hn + c0] =
                make_float2(hnew[1][0], hnew[1][1]);
        }

        float* hnxt = hb + (cur ^ 1) * 1536;
        *(float2*)&hnxt[c0 * 12 + ra] =
            make_float2(hnew[0][0] * (1.f - dn[0]), hnew[1][0] * (1.f - dn[1]));
        *(float2*)&hnxt[c1 * 12 + ra] =
            make_float2(hnew[0][1] * (1.f - dn[0]), hnew[1][1] * (1.f - dn[1]));

        #pragma unroll
        for (int rr = 0; rr < 2; rr++)
            #pragma unroll
            for (int cc = 0; cc < 2; cc++)
                #pragma unroll
                for (int g = 0; g < 3; g++)
                    gx[rr][cc][g] = gxn[rr][cc][g];

        __syncthreads();
        cur ^= 1;
    }
}

// ---------------------------------------------------------------------------
// Heads (measured-best): thread-per-row, h streamed from global.
// ---------------------------------------------------------------------------
__global__ void __launch_bounds__(512, 4) heads_kernel(
    const int* __restrict__ action,
    const float* __restrict__ Wa, const float* __restrict__ ba,
    const float* __restrict__ Wc, const float* __restrict__ bc,
    float* __restrict__ out)
{
    __shared__ float swa[16 * 128];
    __shared__ float swc[128];
    __shared__ float sba[16];
    __shared__ float sbc;

    int tid = threadIdx.x;
    for (int i = tid; i < 16 * 128; i += 512) swa[i] = Wa[i];
    if (tid < 128) swc[tid] = Wc[tid];
    if (tid < 16)  sba[tid] = ba[tid];
    if (tid == 0)  sbc = bc[0];
    __syncthreads();

    size_t row = (size_t)blockIdx.x * 512 + tid;
    const float* hrow = &g_hidden[row * 128];

    float l[16];
    #pragma unroll
    for (int j = 0; j < 16; j++) l[j] = sba[j];
    float v = sbc;

    #pragma unroll 4
    for (int k4 = 0; k4 < 32; k4++) {
        float4 h4 = *(const float4*)(hrow + k4 * 4);
        const float* wa = &swa[k4 * 4];
        #pragma unroll
        for (int j = 0; j < 16; j++) {
            l[j] += wa[j * 128]     * h4.x;
            l[j] += wa[j * 128 + 1] * h4.y;
            l[j] += wa[j * 128 + 2] * h4.z;
            l[j] += wa[j * 128 + 3] * h4.w;
        }
        v += swc[k4 * 4]     * h4.x + swc[k4 * 4 + 1] * h4.y
           + swc[k4 * 4 + 2] * h4.z + swc[k4 * 4 + 3] * h4.w;
    }

    float mx = l[0];
    #pragma unroll
    for (int j = 1; j < 16; j++) mx = fmaxf(mx, l[j]);
    float se = 0.f, pl = 0.f;
    #pragma unroll
    for (int j = 0; j < 16; j++) {
        float e = __expf(l[j] - mx);
        se += e; pl += e * l[j];
    }
    float lse = mx + __logf(se);
    int a = action[row];
    float la = 0.f;
    #pragma unroll
    for (int j = 0; j < 16; j++) la = (a == j) ? l[j] : la;
    out[row * 3 + 0] = la - lse;
    out[row * 3 + 1] = lse - pl / se;
    out[row * 3 + 2] = v;
}

// ---------------------------------------------------------------------------
extern "C" void kernel_launch(void* const* d_in, const int* in_sizes, int n_in,
                              void* d_out, int out_size)
{
    const float* x    = (const float*)d_in[0];
    const float* done = (const float*)d_in[1];
    const int*   act  = (const int*)  d_in[2];
    const float* gru  = (const float*)d_in[3];
    const float* W1   = (const float*)d_in[4];
    const float* b1   = (const float*)d_in[5];
    const float* W2   = (const float*)d_in[6];
    const float* b2   = (const float*)d_in[7];
    const float* Wih  = (const float*)d_in[8];
    const float* bih  = (const float*)d_in[9];
    const float* Whh  = (const float*)d_in[10];
    const float* bhh  = (const float*)d_in[11];
    const float* Wa   = (const float*)d_in[12];
    const float* ba   = (const float*)d_in[13];
    const float* Wc   = (const float*)d_in[14];
    const float* bc   = (const float*)d_in[15];
    float* out = (float*)d_out;

    size_t enc_smem  = (size_t)(64 * SA + 128 * SA) * sizeof(float);   // 101376 B
    size_t scan_smem = (size_t)(49152 + 2 * 1536) * sizeof(float);     // 208896 B

    cudaFuncSetAttribute(encoder_kernel, cudaFuncAttributeMaxDynamicSharedMemorySize, (int)enc_smem);
    cudaFuncSetAttribute(scan_kernel,    cudaFuncAttributeMaxDynamicSharedMemorySize, (int)scan_smem);

    encoder_kernel<<<TBn / 128, 512, enc_smem>>>(x, W1, b1, W2, b2, Wih, bih);
    scan_kernel<<<128, 256, scan_smem>>>(done, gru, Whh, bhh, out);
    heads_kernel<<<TBn / 512, 512>>>(act, Wa, ba, Wc, bc, out);
}

// round 15
// speedup vs baseline: 1.0817x; 1.0817x over previous
#include <cuda_runtime.h>
#include <cstdint>

#define Tn  512
#define Bn  1024
#define Sn  64
#define An  16
#define Hn  128
#define TBn (Tn*Bn)

typedef unsigned long long ull;

__device__ float g_gx[(size_t)TBn * 384];      // gate preactivations [T*B, 3H]
__device__ float g_hidden[(size_t)TBn * Hn];   // hidden states [T*B, H]

// ---------------------------------------------------------------------------
// f32x2 + fast-math helpers
// ---------------------------------------------------------------------------
__device__ __forceinline__ ull pack2(float lo, float hi) {
    ull r;
    asm("mov.b64 %0, {%1, %2};" : "=l"(r)
        : "r"(__float_as_uint(lo)), "r"(__float_as_uint(hi)));
    return r;
}
__device__ __forceinline__ ull dup2(float v) { return pack2(v, v); }
__device__ __forceinline__ void unpack2(ull p, float& lo, float& hi) {
    unsigned int a, b;
    asm("mov.b64 {%0, %1}, %2;" : "=r"(a), "=r"(b) : "l"(p));
    lo = __uint_as_float(a); hi = __uint_as_float(b);
}
__device__ __forceinline__ void fma2(ull& d, ull a, ull b) {
    asm("fma.rn.f32x2 %0, %1, %2, %3;" : "=l"(d) : "l"(a), "l"(b), "l"(d));
}
__device__ __forceinline__ ull add2(ull a, ull b) {
    ull d;
    asm("add.rn.f32x2 %0, %1, %2;" : "=l"(d) : "l"(a), "l"(b));
    return d;
}
__device__ __forceinline__ float tanh_fast(float x) {
    float y; asm("tanh.approx.f32 %0, %1;" : "=f"(y) : "f"(x)); return y;
}
__device__ __forceinline__ float sigmoid_fast(float x) {
    return fmaf(0.5f, tanh_fast(0.5f * x), 0.5f);
}

// ---------------------------------------------------------------------------
// Encoder (R13 measured-best): fused x -> h1 -> h2 -> gx.
// 512 threads, 128 rows/block, 2 blk/SM; 8x4 microtile; in-place ABUF.
// ---------------------------------------------------------------------------
#define SA 132

__device__ __forceinline__ void enc_gemm64(const float* __restrict__ ap,
                                           const float* __restrict__ wp,
                                           ull acc[4][4])
{
    #pragma unroll 4
    for (int k = 0; k < 64; k++) {
        ulonglong2 aA = *(const ulonglong2*)(ap + k * SA);
        ulonglong2 aB = *(const ulonglong2*)(ap + k * SA + 4);
        float4 wv = *(const float4*)(wp + k * SA);
        ull w0 = dup2(wv.x), w1 = dup2(wv.y), w2 = dup2(wv.z), w3 = dup2(wv.w);
        fma2(acc[0][0], aA.x, w0); fma2(acc[1][0], aA.y, w0);
        fma2(acc[2][0], aB.x, w0); fma2(acc[3][0], aB.y, w0);
        fma2(acc[0][1], aA.x, w1); fma2(acc[1][1], aA.y, w1);
        fma2(acc[2][1], aB.x, w1); fma2(acc[3][1], aB.y, w1);
        fma2(acc[0][2], aA.x, w2); fma2(acc[1][2], aA.y, w2);
        fma2(acc[2][2], aB.x, w2); fma2(acc[3][2], aB.y, w2);
        fma2(acc[0][3], aA.x, w3); fma2(acc[1][3], aA.y, w3);
        fma2(acc[2][3], aB.x, w3); fma2(acc[3][3], aB.y, w3);
    }
}

__global__ void __launch_bounds__(512, 2) encoder_kernel(
    const float* __restrict__ x,
    const float* __restrict__ W1, const float* __restrict__ b1,
    const float* __restrict__ W2, const float* __restrict__ b2,
    const float* __restrict__ Wih, const float* __restrict__ bih)
{
    extern __shared__ float sm[];
    float* Wt   = sm;                   // 64*132 floats
    float* ABUF = sm + 64 * SA;         // 128*132 floats

    int tid = threadIdx.x;
    int cg  = tid & 31;
    int rg  = tid >> 5;
    size_t base = (size_t)blockIdx.x * 128;

    for (int idx = tid; idx < 128 * 64; idx += 512) {
        int r = idx >> 6, k = idx & 63;
        ABUF[k * SA + r] = x[(base + r) * 64 + k];
    }
    for (int idx = tid; idx < 64 * 128; idx += 512) {
        int k = idx & 63, j = idx >> 6;
        Wt[k * SA + j] = W1[j * 64 + k];
    }
    __syncthreads();

    ull acc[4][4];

    // Phase A
    #pragma unroll
    for (int c = 0; c < 4; c++) {
        ull bb = dup2(b1[4 * cg + c]);
        acc[0][c] = bb; acc[1][c] = bb; acc[2][c] = bb; acc[3][c] = bb;
    }
    enc_gemm64(ABUF + rg * 8, Wt + 4 * cg, acc);
    __syncthreads();
    #pragma unroll
    for (int c = 0; c < 4; c++) {
        int col = 4 * cg + c;
        float v[8];
        unpack2(acc[0][c], v[0], v[1]); unpack2(acc[1][c], v[2], v[3]);
        unpack2(acc[2][c], v[4], v[5]); unpack2(acc[3][c], v[6], v[7]);
        #pragma unroll
        for (int i = 0; i < 8; i++) v[i] = fmaxf(v[i], 0.f);
        *(float4*)&ABUF[col * SA + rg * 8]     = make_float4(v[0], v[1], v[2], v[3]);
        *(float4*)&ABUF[col * SA + rg * 8 + 4] = make_float4(v[4], v[5], v[6], v[7]);
    }
    __syncthreads();

    // Phase B
    #pragma unroll
    for (int c = 0; c < 4; c++) {
        ull bb = dup2(b2[4 * cg + c]);
        acc[0][c] = bb; acc[1][c] = bb; acc[2][c] = bb; acc[3][c] = bb;
    }
    #pragma unroll 1
    for (int h = 0; h < 2; h++) {
        for (int idx = tid; idx < 64 * 128; idx += 512) {
            int kl = idx & 63, j = idx >> 6;
            Wt[kl * SA + j] = W2[j * 128 + h * 64 + kl];
        }
        __syncthreads();
        enc_gemm64(ABUF + (h * 64) * SA + rg * 8, Wt + 4 * cg, acc);
        __syncthreads();
    }
    #pragma unroll
    for (int c = 0; c < 4; c++) {
        int col = 4 * cg + c;
        float v[8];
        unpack2(acc[0][c], v[0], v[1]); unpack2(acc[1][c], v[2], v[3]);
        unpack2(acc[2][c], v[4], v[5]); unpack2(acc[3][c], v[6], v[7]);
        #pragma unroll
        for (int i = 0; i < 8; i++) v[i] = fmaxf(v[i], 0.f);
        *(float4*)&ABUF[col * SA + rg * 8]     = make_float4(v[0], v[1], v[2], v[3]);
        *(float4*)&ABUF[col * SA + rg * 8 + 4] = make_float4(v[4], v[5], v[6], v[7]);
    }
    __syncthreads();

    // Phase C
    #pragma unroll 1
    for (int pp = 0; pp < 3; pp++) {
        #pragma unroll
        for (int c = 0; c < 4; c++) {
            ull bb = dup2(bih[pp * 128 + 4 * cg + c]);
            acc[0][c] = bb; acc[1][c] = bb; acc[2][c] = bb; acc[3][c] = bb;
        }
        #pragma unroll 1
        for (int h = 0; h < 2; h++) {
            for (int idx = tid; idx < 64 * 128; idx += 512) {
                int kl = idx & 63, j = idx >> 6;
                Wt[kl * SA + j] = Wih[(pp * 128 + j) * 128 + h * 64 + kl];
            }
            __syncthreads();
            enc_gemm64(ABUF + (h * 64) * SA + rg * 8, Wt + 4 * cg, acc);
            __syncthreads();
        }
        #pragma unroll
        for (int p = 0; p < 4; p++) {
            float va[4], vb[4];
            #pragma unroll
            for (int c = 0; c < 4; c++) unpack2(acc[p][c], va[c], vb[c]);
            size_t row0 = base + rg * 8 + 2 * p;
            *(float4*)&g_gx[row0 * 384 + pp * 128 + 4 * cg] =
                make_float4(va[0], va[1], va[2], va[3]);
            *(float4*)&g_gx[(row0 + 1) * 384 + pp * 128 + 4 * cg] =
                make_float4(vb[0], vb[1], vb[2], vb[3]);
        }
    }
}

// ---------------------------------------------------------------------------
// GRU scan (R13 measured-best, kq unroll 16): 128 blocks x 8 rows, 256 threads.
// Thread = (column pair cp, k-quarter kh): lane = (cp&7) + 8*kh, warp = cp>>3.
// Weights lane-linear wln[(kq*3+g)*256 + tid] (float2 = thread's 2 cols).
// h in hT[f][r] stride 12, double-buffered. Butterfly xor 8/16. 1 bar/step.
// ---------------------------------------------------------------------------
__device__ __forceinline__ ull bfly_sum(ull x) {
    x = add2(x, __shfl_xor_sync(0xffffffffu, x, 8));
    x = add2(x, __shfl_xor_sync(0xffffffffu, x, 16));
    return x;
}
__device__ __forceinline__ ull sel4(ull a0, ull a1, ull a2, ull a3, int s) {
    ull x = (s & 1) ? a1 : a0;
    ull y = (s & 1) ? a3 : a2;
    return (s & 2) ? y : x;
}

__global__ void __launch_bounds__(256, 1) scan_kernel(
    const float* __restrict__ done, const float* __restrict__ gru0,
    const float* __restrict__ Whh, const float* __restrict__ bhh,
    float* __restrict__ out)
{
    extern __shared__ float sm[];
    float2* wln = (float2*)sm;              // 96*256 float2 = 49152 floats
    float*  hb  = sm + 49152;               // 2 * 1536 floats

    int tid  = threadIdx.x;
    int lane = tid & 31;
    int cp   = (tid >> 5) * 8 + (lane & 7); // 0..63
    int kh   = lane >> 3;                   // 0..3
    int c0   = 2 * cp, c1 = c0 + 1;
    int ra   = 2 * kh, rb = ra + 1;
    int b0   = blockIdx.x << 3;

    for (int idx = tid; idx < 96 * 256; idx += 256) {
        int kq = idx / 768;
        int rem = idx - kq * 768;
        int g = rem >> 8, t = rem & 255;
        int cpt = (t >> 5) * 8 + (t & 7);
        int kht = (t & 31) >> 3;
        int k = kht * 32 + kq;
        wln[idx] = make_float2(Whh[(g * 128 + 2 * cpt) * 128 + k],
                               Whh[(g * 128 + 2 * cpt + 1) * 128 + k]);
    }
    for (int idx = tid; idx < 1024; idx += 256) {
        int r = idx & 7, f = idx >> 3;
        hb[f * 12 + r] = gru0[(b0 + r) * 128 + f] * (1.f - done[b0 + r]);
    }
    __syncthreads();

    float brv[2] = {bhh[c0], bhh[c1]};
    float bzv[2] = {bhh[128 + c0], bhh[128 + c1]};
    float bnv[2] = {bhh[256 + c0], bhh[256 + c1]};

    float gx[2][2][3];
    #pragma unroll
    for (int rr = 0; rr < 2; rr++) {
        size_t row = (size_t)(b0 + ra + rr);
        float2 t0 = *(const float2*)&g_gx[row * 384 + c0];
        float2 t1 = *(const float2*)&g_gx[row * 384 + 128 + c0];
        float2 t2 = *(const float2*)&g_gx[row * 384 + 256 + c0];
        gx[rr][0][0] = t0.x; gx[rr][1][0] = t0.y;
        gx[rr][0][1] = t1.x; gx[rr][1][1] = t1.y;
        gx[rr][0][2] = t2.x; gx[rr][1][2] = t2.y;
    }

    const float2* wp = wln + tid;
    int cur = 0;

    for (int t = 0; t < Tn; t++) {
        float gxn[2][2][3], dn[2];
        {
            int tnx = (t + 1 < Tn) ? (t + 1) : t;
            #pragma unroll
            for (int rr = 0; rr < 2; rr++) {
                size_t row = (size_t)tnx * Bn + b0 + ra + rr;
                float2 t0 = *(const float2*)&g_gx[row * 384 + c0];
                float2 t1 = *(const float2*)&g_gx[row * 384 + 128 + c0];
                float2 t2 = *(const float2*)&g_gx[row * 384 + 256 + c0];
                gxn[rr][0][0] = t0.x; gxn[rr][1][0] = t0.y;
                gxn[rr][0][1] = t1.x; gxn[rr][1][1] = t1.y;
                gxn[rr][0][2] = t2.x; gxn[rr][1][2] = t2.y;
                dn[rr] = (t + 1 < Tn) ? done[(size_t)(t + 1) * Bn + b0 + ra + rr] : 0.f;
            }
        }

        const float* hbc = hb + cur * 1536;
        const float* hk  = hbc + (kh * 32) * 12;

        ull aR[2][4], aZ[2][4], aN[2][4];
        #pragma unroll
        for (int cc = 0; cc < 2; cc++)
            #pragma unroll
            for (int p = 0; p < 4; p++) { aR[cc][p] = 0; aZ[cc][p] = 0; aN[cc][p] = 0; }

        #pragma unroll 16
        for (int kq = 0; kq < 32; kq++) {
            ulonglong2 hA = *(const ulonglong2*)(hk + kq * 12);
            ulonglong2 hB = *(const ulonglong2*)(hk + kq * 12 + 4);
            float2 wr = wp[(kq * 3 + 0) * 256];
            float2 wz = wp[(kq * 3 + 1) * 256];
            float2 wn = wp[(kq * 3 + 2) * 256];
            ull wr0 = dup2(wr.x), wr1 = dup2(wr.y);
            ull wz0 = dup2(wz.x), wz1 = dup2(wz.y);
            ull wn0 = dup2(wn.x), wn1 = dup2(wn.y);
            fma2(aR[0][0], hA.x, wr0); fma2(aR[0][1], hA.y, wr0);
            fma2(aR[0][2], hB.x, wr0); fma2(aR[0][3], hB.y, wr0);
            fma2(aR[1][0], hA.x, wr1); fma2(aR[1][1], hA.y, wr1);
            fma2(aR[1][2], hB.x, wr1); fma2(aR[1][3], hB.y, wr1);
            fma2(aZ[0][0], hA.x, wz0); fma2(aZ[0][1], hA.y, wz0);
            fma2(aZ[0][2], hB.x, wz0); fma2(aZ[0][3], hB.y, wz0);
            fma2(aZ[1][0], hA.x, wz1); fma2(aZ[1][1], hA.y, wz1);
            fma2(aZ[1][2], hB.x, wz1); fma2(aZ[1][3], hB.y, wz1);
            fma2(aN[0][0], hA.x, wn0); fma2(aN[0][1], hA.y, wn0);
            fma2(aN[0][2], hB.x, wn0); fma2(aN[0][3], hB.y, wn0);
            fma2(aN[1][0], hA.x, wn1); fma2(aN[1][1], hA.y, wn1);
            fma2(aN[1][2], hB.x, wn1); fma2(aN[1][3], hB.y, wn1);
        }

        #pragma unroll
        for (int cc = 0; cc < 2; cc++)
            #pragma unroll
            for (int p = 0; p < 4; p++) {
                aR[cc][p] = bfly_sum(aR[cc][p]);
                aZ[cc][p] = bfly_sum(aZ[cc][p]);
                aN[cc][p] = bfly_sum(aN[cc][p]);
            }

        float sR[2][2], sZ[2][2], sN[2][2];
        #pragma unroll
        for (int cc = 0; cc < 2; cc++) {
            float lo, hi;
            unpack2(sel4(aR[cc][0], aR[cc][1], aR[cc][2], aR[cc][3], kh), lo, hi);
            sR[0][cc] = lo; sR[1][cc] = hi;
            unpack2(sel4(aZ[cc][0], aZ[cc][1], aZ[cc][2], aZ[cc][3], kh), lo, hi);
            sZ[0][cc] = lo; sZ[1][cc] = hi;
            unpack2(sel4(aN[cc][0], aN[cc][1], aN[cc][2], aN[cc][3], kh), lo, hi);
            sN[0][cc] = lo; sN[1][cc] = hi;
        }

        float2 hoA = *(const float2*)&hbc[c0 * 12 + ra];
        float2 hoB = *(const float2*)&hbc[c1 * 12 + ra];
        float ho[2][2] = {{hoA.x, hoB.x}, {hoA.y, hoB.y}};

        float hnew[2][2];
        #pragma unroll
        for (int rr = 0; rr < 2; rr++)
            #pragma unroll
            for (int cc = 0; cc < 2; cc++) {
                float sr = sR[rr][cc] + brv[cc] + gx[rr][cc][0];
                float sz = sZ[rr][cc] + bzv[cc] + gx[rr][cc][1];
                float sn = sN[rr][cc] + bnv[cc];
                float rg = sigmoid_fast(sr);
                float zg = sigmoid_fast(sz);
                float ng = tanh_fast(gx[rr][cc][2] + rg * sn);
                hnew[rr][cc] = (1.f - zg) * ng + zg * ho[rr][cc];
            }

        *(float2*)&g_hidden[((size_t)t * Bn + b0 + ra) * Hn + c0] =
            make_float2(hnew[0][0], hnew[0][1]);
        *(float2*)&g_hidden[((size_t)t * Bn + b0 + rb) * Hn + c0] =
            make_float2(hnew[1][0], hnew[1][1]);
        if (t == Tn - 1) {
            *(float2*)&out[(size_t)TBn * 3 + (b0 + ra) * Hn + c0] =
                make_float2(hnew[0][0], hnew[0][1]);
            *(float2*)&out[(size_t)TBn * 3 + (b0 + rb) * Hn + c0] =
                make_float2(hnew[1][0], hnew[1][1]);
        }

        float* hnxt = hb + (cur ^ 1) * 1536;
        *(float2*)&hnxt[c0 * 12 + ra] =
            make_float2(hnew[0][0] * (1.f - dn[0]), hnew[1][0] * (1.f - dn[1]));
        *(float2*)&hnxt[c1 * 12 + ra] =
            make_float2(hnew[0][1] * (1.f - dn[0]), hnew[1][1] * (1.f - dn[1]));

        #pragma unroll
        for (int rr = 0; rr < 2; rr++)
            #pragma unroll
            for (int cc = 0; cc < 2; cc++)
                #pragma unroll
                for (int g = 0; g < 3; g++)
                    gx[rr][cc][g] = gxn[rr][cc][g];

        __syncthreads();
        cur ^= 1;
    }
}

// ---------------------------------------------------------------------------
// Heads (measured-best): thread-per-row, h streamed from global.
// ---------------------------------------------------------------------------
__global__ void __launch_bounds__(512, 4) heads_kernel(
    const int* __restrict__ action,
    const float* __restrict__ Wa, const float* __restrict__ ba,
    const float* __restrict__ Wc, const float* __restrict__ bc,
    float* __restrict__ out)
{
    __shared__ float swa[16 * 128];
    __shared__ float swc[128];
    __shared__ float sba[16];
    __shared__ float sbc;

    int tid = threadIdx.x;
    for (int i = tid; i < 16 * 128; i += 512) swa[i] = Wa[i];
    if (tid < 128) swc[tid] = Wc[tid];
    if (tid < 16)  sba[tid] = ba[tid];
    if (tid == 0)  sbc = bc[0];
    __syncthreads();

    size_t row = (size_t)blockIdx.x * 512 + tid;
    const float* hrow = &g_hidden[row * 128];

    float l[16];
    #pragma unroll
    for (int j = 0; j < 16; j++) l[j] = sba[j];
    float v = sbc;

    #pragma unroll 4
    for (int k4 = 0; k4 < 32; k4++) {
        float4 h4 = *(const float4*)(hrow + k4 * 4);
        const float* wa = &swa[k4 * 4];
        #pragma unroll
        for (int j = 0; j < 16; j++) {
            l[j] += wa[j * 128]     * h4.x;
            l[j] += wa[j * 128 + 1] * h4.y;
            l[j] += wa[j * 128 + 2] * h4.z;
            l[j] += wa[j * 128 + 3] * h4.w;
        }
        v += swc[k4 * 4]     * h4.x + swc[k4 * 4 + 1] * h4.y
           + swc[k4 * 4 + 2] * h4.z + swc[k4 * 4 + 3] * h4.w;
    }

    float mx = l[0];
    #pragma unroll
    for (int j = 1; j < 16; j++) mx = fmaxf(mx, l[j]);
    float se = 0.f, pl = 0.f;
    #pragma unroll
    for (int j = 0; j < 16; j++) {
        float e = __expf(l[j] - mx);
        se += e; pl += e * l[j];
    }
    float lse = mx + __logf(se);
    int a = action[row];
    float la = 0.f;
    #pragma unroll
    for (int j = 0; j < 16; j++) la = (a == j) ? l[j] : la;
    out[row * 3 + 0] = la - lse;
    out[row * 3 + 1] = lse - pl / se;
    out[row * 3 + 2] = v;
}

// ---------------------------------------------------------------------------
extern "C" void kernel_launch(void* const* d_in, const int* in_sizes, int n_in,
                              void* d_out, int out_size)
{
    const float* x    = (const float*)d_in[0];
    const float* done = (const float*)d_in[1];
    const int*   act  = (const int*)  d_in[2];
    const float* gru  = (const float*)d_in[3];
    const float* W1   = (const float*)d_in[4];
    const float* b1   = (const float*)d_in[5];
    const float* W2   = (const float*)d_in[6];
    const float* b2   = (const float*)d_in[7];
    const float* Wih  = (const float*)d_in[8];
    const float* bih  = (const float*)d_in[9];
    const float* Whh  = (const float*)d_in[10];
    const float* bhh  = (const float*)d_in[11];
    const float* Wa   = (const float*)d_in[12];
    const float* ba   = (const float*)d_in[13];
    const float* Wc   = (const float*)d_in[14];
    const float* bc   = (const float*)d_in[15];
    float* out = (float*)d_out;

    size_t enc_smem  = (size_t)(64 * SA + 128 * SA) * sizeof(float);   // 101376 B
    size_t scan_smem = (size_t)(49152 + 2 * 1536) * sizeof(float);     // 208896 B

    cudaFuncSetAttribute(encoder_kernel, cudaFuncAttributeMaxDynamicSharedMemorySize, (int)enc_smem);
    cudaFuncSetAttribute(scan_kernel,    cudaFuncAttributeMaxDynamicSharedMemorySize, (int)scan_smem);

    encoder_kernel<<<TBn / 128, 512, enc_smem>>>(x, W1, b1, W2, b2, Wih, bih);
    scan_kernel<<<128, 256, scan_smem>>>(done, gru, Whh, bhh, out);
    heads_kernel<<<TBn / 512, 512>>>(act, Wa, ba, Wc, bc, out);
}

// round 16
// speedup vs baseline: 1.1240x; 1.0392x over previous
#include <cuda_runtime.h>
#include <cstdint>

#define Tn  512
#define Bn  1024
#define Sn  64
#define An  16
#define Hn  128
#define TBn (Tn*Bn)

typedef unsigned long long ull;

__device__ float g_gx[(size_t)TBn * 384];      // gate preactivations [T*B, 3H]
__device__ float g_hidden[(size_t)TBn * Hn];   // hidden states [T*B, H]

// ---------------------------------------------------------------------------
// f32x2 + fast-math helpers
// ---------------------------------------------------------------------------
__device__ __forceinline__ ull pack2(float lo, float hi) {
    ull r;
    asm("mov.b64 %0, {%1, %2};" : "=l"(r)
        : "r"(__float_as_uint(lo)), "r"(__float_as_uint(hi)));
    return r;
}
__device__ __forceinline__ ull dup2(float v) { return pack2(v, v); }
__device__ __forceinline__ void unpack2(ull p, float& lo, float& hi) {
    unsigned int a, b;
    asm("mov.b64 {%0, %1}, %2;" : "=r"(a), "=r"(b) : "l"(p));
    lo = __uint_as_float(a); hi = __uint_as_float(b);
}
__device__ __forceinline__ void fma2(ull& d, ull a, ull b) {
    asm("fma.rn.f32x2 %0, %1, %2, %3;" : "=l"(d) : "l"(a), "l"(b), "l"(d));
}
__device__ __forceinline__ ull add2(ull a, ull b) {
    ull d;
    asm("add.rn.f32x2 %0, %1, %2;" : "=l"(d) : "l"(a), "l"(b));
    return d;
}
__device__ __forceinline__ float tanh_fast(float x) {
    float y; asm("tanh.approx.f32 %0, %1;" : "=f"(y) : "f"(x)); return y;
}
__device__ __forceinline__ float sigmoid_fast(float x) {
    return fmaf(0.5f, tanh_fast(0.5f * x), 0.5f);
}

// ---------------------------------------------------------------------------
// Encoder (R13/R15 measured-best, unchanged): fused x -> h1 -> h2 -> gx.
// 512 threads, 128 rows/block, 2 blk/SM; 8x4 microtile; in-place ABUF.
// ---------------------------------------------------------------------------
#define SA 132

__device__ __forceinline__ void enc_gemm64(const float* __restrict__ ap,
                                           const float* __restrict__ wp,
                                           ull acc[4][4])
{
    #pragma unroll 4
    for (int k = 0; k < 64; k++) {
        ulonglong2 aA = *(const ulonglong2*)(ap + k * SA);
        ulonglong2 aB = *(const ulonglong2*)(ap + k * SA + 4);
        float4 wv = *(const float4*)(wp + k * SA);
        ull w0 = dup2(wv.x), w1 = dup2(wv.y), w2 = dup2(wv.z), w3 = dup2(wv.w);
        fma2(acc[0][0], aA.x, w0); fma2(acc[1][0], aA.y, w0);
        fma2(acc[2][0], aB.x, w0); fma2(acc[3][0], aB.y, w0);
        fma2(acc[0][1], aA.x, w1); fma2(acc[1][1], aA.y, w1);
        fma2(acc[2][1], aB.x, w1); fma2(acc[3][1], aB.y, w1);
        fma2(acc[0][2], aA.x, w2); fma2(acc[1][2], aA.y, w2);
        fma2(acc[2][2], aB.x, w2); fma2(acc[3][2], aB.y, w2);
        fma2(acc[0][3], aA.x, w3); fma2(acc[1][3], aA.y, w3);
        fma2(acc[2][3], aB.x, w3); fma2(acc[3][3], aB.y, w3);
    }
}

__global__ void __launch_bounds__(512, 2) encoder_kernel(
    const float* __restrict__ x,
    const float* __restrict__ W1, const float* __restrict__ b1,
    const float* __restrict__ W2, const float* __restrict__ b2,
    const float* __restrict__ Wih, const float* __restrict__ bih)
{
    extern __shared__ float sm[];
    float* Wt   = sm;                   // 64*132 floats
    float* ABUF = sm + 64 * SA;         // 128*132 floats

    int tid = threadIdx.x;
    int cg  = tid & 31;
    int rg  = tid >> 5;
    size_t base = (size_t)blockIdx.x * 128;

    for (int idx = tid; idx < 128 * 64; idx += 512) {
        int r = idx >> 6, k = idx & 63;
        ABUF[k * SA + r] = x[(base + r) * 64 + k];
    }
    for (int idx = tid; idx < 64 * 128; idx += 512) {
        int k = idx & 63, j = idx >> 6;
        Wt[k * SA + j] = W1[j * 64 + k];
    }
    __syncthreads();

    ull acc[4][4];

    // Phase A
    #pragma unroll
    for (int c = 0; c < 4; c++) {
        ull bb = dup2(b1[4 * cg + c]);
        acc[0][c] = bb; acc[1][c] = bb; acc[2][c] = bb; acc[3][c] = bb;
    }
    enc_gemm64(ABUF + rg * 8, Wt + 4 * cg, acc);
    __syncthreads();
    #pragma unroll
    for (int c = 0; c < 4; c++) {
        int col = 4 * cg + c;
        float v[8];
        unpack2(acc[0][c], v[0], v[1]); unpack2(acc[1][c], v[2], v[3]);
        unpack2(acc[2][c], v[4], v[5]); unpack2(acc[3][c], v[6], v[7]);
        #pragma unroll
        for (int i = 0; i < 8; i++) v[i] = fmaxf(v[i], 0.f);
        *(float4*)&ABUF[col * SA + rg * 8]     = make_float4(v[0], v[1], v[2], v[3]);
        *(float4*)&ABUF[col * SA + rg * 8 + 4] = make_float4(v[4], v[5], v[6], v[7]);
    }
    __syncthreads();

    // Phase B
    #pragma unroll
    for (int c = 0; c < 4; c++) {
        ull bb = dup2(b2[4 * cg + c]);
        acc[0][c] = bb; acc[1][c] = bb; acc[2][c] = bb; acc[3][c] = bb;
    }
    #pragma unroll 1
    for (int h = 0; h < 2; h++) {
        for (int idx = tid; idx < 64 * 128; idx += 512) {
            int kl = idx & 63, j = idx >> 6;
            Wt[kl * SA + j] = W2[j * 128 + h * 64 + kl];
        }
        __syncthreads();
        enc_gemm64(ABUF + (h * 64) * SA + rg * 8, Wt + 4 * cg, acc);
        __syncthreads();
    }
    #pragma unroll
    for (int c = 0; c < 4; c++) {
        int col = 4 * cg + c;
        float v[8];
        unpack2(acc[0][c], v[0], v[1]); unpack2(acc[1][c], v[2], v[3]);
        unpack2(acc[2][c], v[4], v[5]); unpack2(acc[3][c], v[6], v[7]);
        #pragma unroll
        for (int i = 0; i < 8; i++) v[i] = fmaxf(v[i], 0.f);
        *(float4*)&ABUF[col * SA + rg * 8]     = make_float4(v[0], v[1], v[2], v[3]);
        *(float4*)&ABUF[col * SA + rg * 8 + 4] = make_float4(v[4], v[5], v[6], v[7]);
    }
    __syncthreads();

    // Phase C
    #pragma unroll 1
    for (int pp = 0; pp < 3; pp++) {
        #pragma unroll
        for (int c = 0; c < 4; c++) {
            ull bb = dup2(bih[pp * 128 + 4 * cg + c]);
            acc[0][c] = bb; acc[1][c] = bb; acc[2][c] = bb; acc[3][c] = bb;
        }
        #pragma unroll 1
        for (int h = 0; h < 2; h++) {
            for (int idx = tid; idx < 64 * 128; idx += 512) {
                int kl = idx & 63, j = idx >> 6;
                Wt[kl * SA + j] = Wih[(pp * 128 + j) * 128 + h * 64 + kl];
            }
            __syncthreads();
            enc_gemm64(ABUF + (h * 64) * SA + rg * 8, Wt + 4 * cg, acc);
            __syncthreads();
        }
        #pragma unroll
        for (int p = 0; p < 4; p++) {
            float va[4], vb[4];
            #pragma unroll
            for (int c = 0; c < 4; c++) unpack2(acc[p][c], va[c], vb[c]);
            size_t row0 = base + rg * 8 + 2 * p;
            *(float4*)&g_gx[row0 * 384 + pp * 128 + 4 * cg] =
                make_float4(va[0], va[1], va[2], va[3]);
            *(float4*)&g_gx[(row0 + 1) * 384 + pp * 128 + 4 * cg] =
                make_float4(vb[0], vb[1], vb[2], vb[3]);
        }
    }
}

// ---------------------------------------------------------------------------
// GRU scan (R15 + REDUCE-SCATTER epilogue): 128 blocks x 8 rows, 256 threads.
// Thread = (column pair cp, k-quarter kh): lane = (cp&7) + 8*kh, warp = cp>>3.
// Weights lane-linear wln[(kq*3+g)*256 + tid]; h hT[f][r] stride 12, dbuf.
// Reduce-scatter: lane-selected shfl operands deliver row-pair kh's full sum
// in 3 ull-shfls + 3 adds per 4-acc group (vs 8+8 for all-gather butterfly).
// ---------------------------------------------------------------------------
__device__ __forceinline__ ull shfl_xor64(ull x, int m) {
    return __shfl_xor_sync(0xffffffffu, x, m);
}

// Reduce 4 per-quarter partials (p = row-pair index) so THIS lane ends with
// the full sum for its own row pair p* = kh (b = kh&1, c = kh>>1).
// Step1 (xor 8, flips b): send a[1-b], a[3-b]; add partner's into a[b], a[2+b].
// Step2 (xor 16, flips c): keep = (c ? keepB : keepA); swap-add with partner.
__device__ __forceinline__ ull rscat(ull a0, ull a1, ull a2, ull a3, int b, int c)
{
    ull keepA = b ? a1 : a0;       // partial for p = b
    ull keepB = b ? a3 : a2;       // partial for p = 2+b
    ull sendA = b ? a0 : a1;       // partner's p = b'
    ull sendB = b ? a2 : a3;       // partner's p = 2+b'
    keepA = add2(keepA, shfl_xor64(sendA, 8));
    keepB = add2(keepB, shfl_xor64(sendB, 8));
    ull keep = c ? keepB : keepA;  // p* = 2c + b
    ull send = c ? keepA : keepB;  // what partner (c^1) needs
    return add2(keep, shfl_xor64(send, 16));
}

__global__ void __launch_bounds__(256, 1) scan_kernel(
    const float* __restrict__ done, const float* __restrict__ gru0,
    const float* __restrict__ Whh, const float* __restrict__ bhh,
    float* __restrict__ out)
{
    extern __shared__ float sm[];
    float2* wln = (float2*)sm;              // 96*256 float2 = 49152 floats
    float*  hb  = sm + 49152;               // 2 * 1536 floats

    int tid  = threadIdx.x;
    int lane = tid & 31;
    int cp   = (tid >> 5) * 8 + (lane & 7); // 0..63
    int kh   = lane >> 3;                   // 0..3
    int bsel = kh & 1, csel = kh >> 1;
    int c0   = 2 * cp, c1 = c0 + 1;
    int ra   = 2 * kh, rb = ra + 1;
    int b0   = blockIdx.x << 3;

    for (int idx = tid; idx < 96 * 256; idx += 256) {
        int kq = idx / 768;
        int rem = idx - kq * 768;
        int g = rem >> 8, t = rem & 255;
        int cpt = (t >> 5) * 8 + (t & 7);
        int kht = (t & 31) >> 3;
        int k = kht * 32 + kq;
        wln[idx] = make_float2(Whh[(g * 128 + 2 * cpt) * 128 + k],
                               Whh[(g * 128 + 2 * cpt + 1) * 128 + k]);
    }
    for (int idx = tid; idx < 1024; idx += 256) {
        int r = idx & 7, f = idx >> 3;
        hb[f * 12 + r] = gru0[(b0 + r) * 128 + f] * (1.f - done[b0 + r]);
    }
    __syncthreads();

    float brv[2] = {bhh[c0], bhh[c1]};
    float bzv[2] = {bhh[128 + c0], bhh[128 + c1]};
    float bnv[2] = {bhh[256 + c0], bhh[256 + c1]};

    float gx[2][2][3];
    #pragma unroll
    for (int rr = 0; rr < 2; rr++) {
        size_t row = (size_t)(b0 + ra + rr);
        float2 t0 = *(const float2*)&g_gx[row * 384 + c0];
        float2 t1 = *(const float2*)&g_gx[row * 384 + 128 + c0];
        float2 t2 = *(const float2*)&g_gx[row * 384 + 256 + c0];
        gx[rr][0][0] = t0.x; gx[rr][1][0] = t0.y;
        gx[rr][0][1] = t1.x; gx[rr][1][1] = t1.y;
        gx[rr][0][2] = t2.x; gx[rr][1][2] = t2.y;
    }

    const float2* wp = wln + tid;
    int cur = 0;

    for (int t = 0; t < Tn; t++) {
        float gxn[2][2][3], dn[2];
        {
            int tnx = (t + 1 < Tn) ? (t + 1) : t;
            #pragma unroll
            for (int rr = 0; rr < 2; rr++) {
                size_t row = (size_t)tnx * Bn + b0 + ra + rr;
                float2 t0 = *(const float2*)&g_gx[row * 384 + c0];
                float2 t1 = *(const float2*)&g_gx[row * 384 + 128 + c0];
                float2 t2 = *(const float2*)&g_gx[row * 384 + 256 + c0];
                gxn[rr][0][0] = t0.x; gxn[rr][1][0] = t0.y;
                gxn[rr][0][1] = t1.x; gxn[rr][1][1] = t1.y;
                gxn[rr][0][2] = t2.x; gxn[rr][1][2] = t2.y;
                dn[rr] = (t + 1 < Tn) ? done[(size_t)(t + 1) * Bn + b0 + ra + rr] : 0.f;
            }
        }

        const float* hbc = hb + cur * 1536;
        const float* hk  = hbc + (kh * 32) * 12;

        ull aR[2][4], aZ[2][4], aN[2][4];
        #pragma unroll
        for (int cc = 0; cc < 2; cc++)
            #pragma unroll
            for (int p = 0; p < 4; p++) { aR[cc][p] = 0; aZ[cc][p] = 0; aN[cc][p] = 0; }

        #pragma unroll 16
        for (int kq = 0; kq < 32; kq++) {
            ulonglong2 hA = *(const ulonglong2*)(hk + kq * 12);
            ulonglong2 hB = *(const ulonglong2*)(hk + kq * 12 + 4);
            float2 wr = wp[(kq * 3 + 0) * 256];
            float2 wz = wp[(kq * 3 + 1) * 256];
            float2 wn = wp[(kq * 3 + 2) * 256];
            ull wr0 = dup2(wr.x), wr1 = dup2(wr.y);
            ull wz0 = dup2(wz.x), wz1 = dup2(wz.y);
            ull wn0 = dup2(wn.x), wn1 = dup2(wn.y);
            fma2(aR[0][0], hA.x, wr0); fma2(aR[0][1], hA.y, wr0);
            fma2(aR[0][2], hB.x, wr0); fma2(aR[0][3], hB.y, wr0);
            fma2(aR[1][0], hA.x, wr1); fma2(aR[1][1], hA.y, wr1);
            fma2(aR[1][2], hB.x, wr1); fma2(aR[1][3], hB.y, wr1);
            fma2(aZ[0][0], hA.x, wz0); fma2(aZ[0][1], hA.y, wz0);
            fma2(aZ[0][2], hB.x, wz0); fma2(aZ[0][3], hB.y, wz0);
            fma2(aZ[1][0], hA.x, wz1); fma2(aZ[1][1], hA.y, wz1);
            fma2(aZ[1][2], hB.x, wz1); fma2(aZ[1][3], hB.y, wz1);
            fma2(aN[0][0], hA.x, wn0); fma2(aN[0][1], hA.y, wn0);
            fma2(aN[0][2], hB.x, wn0); fma2(aN[0][3], hB.y, wn0);
            fma2(aN[1][0], hA.x, wn1); fma2(aN[1][1], hA.y, wn1);
            fma2(aN[1][2], hB.x, wn1); fma2(aN[1][3], hB.y, wn1);
        }

        // reduce-scatter: each lane gets ONLY its row pair's full sums
        float sR[2][2], sZ[2][2], sN[2][2];
        #pragma unroll
        for (int cc = 0; cc < 2; cc++) {
            float lo, hi;
            unpack2(rscat(aR[cc][0], aR[cc][1], aR[cc][2], aR[cc][3], bsel, csel), lo, hi);
            sR[0][cc] = lo; sR[1][cc] = hi;
            unpack2(rscat(aZ[cc][0], aZ[cc][1], aZ[cc][2], aZ[cc][3], bsel, csel), lo, hi);
            sZ[0][cc] = lo; sZ[1][cc] = hi;
            unpack2(rscat(aN[cc][0], aN[cc][1], aN[cc][2], aN[cc][3], bsel, csel), lo, hi);
            sN[0][cc] = lo; sN[1][cc] = hi;
        }

        float2 hoA = *(const float2*)&hbc[c0 * 12 + ra];
        float2 hoB = *(const float2*)&hbc[c1 * 12 + ra];
        float ho[2][2] = {{hoA.x, hoB.x}, {hoA.y, hoB.y}};

        float hnew[2][2];
        #pragma unroll
        for (int rr = 0; rr < 2; rr++)
            #pragma unroll
            for (int cc = 0; cc < 2; cc++) {
                float sr = sR[rr][cc] + brv[cc] + gx[rr][cc][0];
                float sz = sZ[rr][cc] + bzv[cc] + gx[rr][cc][1];
                float sn = sN[rr][cc] + bnv[cc];
                float rg = sigmoid_fast(sr);
                float zg = sigmoid_fast(sz);
                float ng = tanh_fast(gx[rr][cc][2] + rg * sn);
                hnew[rr][cc] = (1.f - zg) * ng + zg * ho[rr][cc];
            }

        *(float2*)&g_hidden[((size_t)t * Bn + b0 + ra) * Hn + c0] =
            make_float2(hnew[0][0], hnew[0][1]);
        *(float2*)&g_hidden[((size_t)t * Bn + b0 + rb) * Hn + c0] =
            make_float2(hnew[1][0], hnew[1][1]);
        if (t == Tn - 1) {
            *(float2*)&out[(size_t)TBn * 3 + (b0 + ra) * Hn + c0] =
                make_float2(hnew[0][0], hnew[0][1]);
            *(float2*)&out[(size_t)TBn * 3 + (b0 + rb) * Hn + c0] =
                make_float2(hnew[1][0], hnew[1][1]);
        }

        float* hnxt = hb + (cur ^ 1) * 1536;
        *(float2*)&hnxt[c0 * 12 + ra] =
            make_float2(hnew[0][0] * (1.f - dn[0]), hnew[1][0] * (1.f - dn[1]));
        *(float2*)&hnxt[c1 * 12 + ra] =
            make_float2(hnew[0][1] * (1.f - dn[0]), hnew[1][1] * (1.f - dn[1]));

        #pragma unroll
        for (int rr = 0; rr < 2; rr++)
            #pragma unroll
            for (int cc = 0; cc < 2; cc++)
                #pragma unroll
                for (int g = 0; g < 3; g++)
                    gx[rr][cc][g] = gxn[rr][cc][g];

        __syncthreads();
        cur ^= 1;
    }
}

// ---------------------------------------------------------------------------
// Heads (measured-best): thread-per-row, h streamed from global.
// ---------------------------------------------------------------------------
__global__ void __launch_bounds__(512, 4) heads_kernel(
    const int* __restrict__ action,
    const float* __restrict__ Wa, const float* __restrict__ ba,
    const float* __restrict__ Wc, const float* __restrict__ bc,
    float* __restrict__ out)
{
    __shared__ float swa[16 * 128];
    __shared__ float swc[128];
    __shared__ float sba[16];
    __shared__ float sbc;

    int tid = threadIdx.x;
    for (int i = tid; i < 16 * 128; i += 512) swa[i] = Wa[i];
    if (tid < 128) swc[tid] = Wc[tid];
    if (tid < 16)  sba[tid] = ba[tid];
    if (tid == 0)  sbc = bc[0];
    __syncthreads();

    size_t row = (size_t)blockIdx.x * 512 + tid;
    const float* hrow = &g_hidden[row * 128];

    float l[16];
    #pragma unroll
    for (int j = 0; j < 16; j++) l[j] = sba[j];
    float v = sbc;

    #pragma unroll 4
    for (int k4 = 0; k4 < 32; k4++) {
        float4 h4 = *(const float4*)(hrow + k4 * 4);
        const float* wa = &swa[k4 * 4];
        #pragma unroll
        for (int j = 0; j < 16; j++) {
            l[j] += wa[j * 128]     * h4.x;
            l[j] += wa[j * 128 + 1] * h4.y;
            l[j] += wa[j * 128 + 2] * h4.z;
            l[j] += wa[j * 128 + 3] * h4.w;
        }
        v += swc[k4 * 4]     * h4.x + swc[k4 * 4 + 1] * h4.y
           + swc[k4 * 4 + 2] * h4.z + swc[k4 * 4 + 3] * h4.w;
    }

    float mx = l[0];
    #pragma unroll
    for (int j = 1; j < 16; j++) mx = fmaxf(mx, l[j]);
    float se = 0.f, pl = 0.f;
    #pragma unroll
    for (int j = 0; j < 16; j++) {
        float e = __expf(l[j] - mx);
        se += e; pl += e * l[j];
    }
    float lse = mx + __logf(se);
    int a = action[row];
    float la = 0.f;
    #pragma unroll
    for (int j = 0; j < 16; j++) la = (a == j) ? l[j] : la;
    out[row * 3 + 0] = la - lse;
    out[row * 3 + 1] = lse - pl / se;
    out[row * 3 + 2] = v;
}

// ---------------------------------------------------------------------------
extern "C" void kernel_launch(void* const* d_in, const int* in_sizes, int n_in,
                              void* d_out, int out_size)
{
    const float* x    = (const float*)d_in[0];
    const float* done = (const float*)d_in[1];
    const int*   act  = (const int*)  d_in[2];
    const float* gru  = (const float*)d_in[3];
    const float* W1   = (const float*)d_in[4];
    const float* b1   = (const float*)d_in[5];
    const float* W2   = (const float*)d_in[6];
    const float* b2   = (const float*)d_in[7];
    const float* Wih  = (const float*)d_in[8];
    const float* bih  = (const float*)d_in[9];
    const float* Whh  = (const float*)d_in[10];
    const float* bhh  = (const float*)d_in[11];
    const float* Wa   = (const float*)d_in[12];
    const float* ba   = (const float*)d_in[13];
    const float* Wc   = (const float*)d_in[14];
    const float* bc   = (const float*)d_in[15];
    float* out = (float*)d_out;

    size_t enc_smem  = (size_t)(64 * SA + 128 * SA) * sizeof(float);   // 101376 B
    size_t scan_smem = (size_t)(49152 + 2 * 1536) * sizeof(float);     // 208896 B

    cudaFuncSetAttribute(encoder_kernel, cudaFuncAttributeMaxDynamicSharedMemorySize, (int)enc_smem);
    cudaFuncSetAttribute(scan_kernel,    cudaFuncAttributeMaxDynamicSharedMemorySize, (int)scan_smem);

    encoder_kernel<<<TBn / 128, 512, enc_smem>>>(x, W1, b1, W2, b2, Wih, bih);
    scan_kernel<<<128, 256, scan_smem>>>(done, gru, Whh, bhh, out);
    heads_kernel<<<TBn / 512, 512>>>(act, Wa, ba, Wc, bc, out);
}